// round 5
// baseline (speedup 1.0000x reference)
#include <cuda_runtime.h>
#include <cstdint>

#define DD 128
#define MAXM 200000
#define MAXR 256
#define MAXB 8

// -------- scratch (static device memory; no allocs allowed) --------
__device__ float g_Hs[(size_t)MAXM * DD];   // hidden @ Ws^T      (102.4 MB)
__device__ float g_agg[(size_t)MAXM * DD];  // segment_sum output (102.4 MB)
__device__ int   g_deg[MAXM];
__device__ float g_Rr[MAXR * DD];           // rela_embed @ Wr^T
__device__ float g_Qq[MAXB * DD];           // query @ Wqr^T + b
__device__ float g_Wf[DD * DD];             // (mlp2 @ mlp1)^T   -- stored [k][n]
__device__ float g_bf[DD];                  // mlp2 @ b1 + b2
__device__ float g_WsT[DD * DD];            // Ws_attn_w^T       -- stored [k][n]

// -------- packed f32x2 helpers (sm_103a FFMA2 pipe: 2 FMA / instr) --------
__device__ __forceinline__ unsigned long long pack2(float lo, float hi) {
    unsigned long long r;
    asm("mov.b64 %0, {%1,%2};" : "=l"(r) : "f"(lo), "f"(hi));
    return r;
}
__device__ __forceinline__ void fma2(unsigned long long& acc, unsigned long long a, unsigned long long b) {
    asm("fma.rn.f32x2 %0, %1, %2, %0;" : "+l"(acc) : "l"(a), "l"(b));
}
__device__ __forceinline__ float2 unpack2(unsigned long long v) {
    float lo, hi;
    asm("mov.b64 {%0,%1}, %2;" : "=f"(lo), "=f"(hi) : "l"(v));
    return make_float2(lo, hi);
}

// -------- tiny precompute: WfT, bf, Rr, Qq, WsT --------
__global__ void prep_kernel(const float* __restrict__ mlp1_w, const float* __restrict__ mlp1_b,
                            const float* __restrict__ mlp2_w, const float* __restrict__ mlp2_b,
                            const float* __restrict__ rela,   const float* __restrict__ Wr,
                            const float* __restrict__ query,  const float* __restrict__ Wqr,
                            const float* __restrict__ Wqr_b,  const float* __restrict__ Ws,
                            int R, int B)
{
    int t = threadIdx.x;
    int bx = blockIdx.x;
    if (bx < DD) {
        int i = bx;                           // output dim (n) of fused weight
        float acc = 0.f;
        for (int j = 0; j < DD; j++) acc += mlp2_w[i * DD + j] * mlp1_w[j * DD + t];
        g_Wf[t * DD + i] = acc;               // store TRANSPOSED: [k][n]
        __shared__ float s[DD];
        s[t] = mlp2_w[i * DD + t] * mlp1_b[t];
        __syncthreads();
        if (t == 0) {
            float b = 0.f;
            for (int j = 0; j < DD; j++) b += s[j];
            g_bf[i] = b + mlp2_b[i];
        }
    } else if (bx < 2 * DD) {
        int n = bx - DD;                      // transpose Ws: g_WsT[k][n] = Ws[n][k]
        g_WsT[t * DD + n] = Ws[n * DD + t];
    } else if (bx < 2 * DD + R) {
        int r = bx - 2 * DD;                  // Rr[r][t] = rela[r]·Wr[t]
        float acc = 0.f;
        for (int d = 0; d < DD; d++) acc += rela[r * DD + d] * Wr[t * DD + d];
        g_Rr[r * DD + t] = acc;
    } else {
        int b = bx - 2 * DD - R;              // Qq[b][t] = query[b]·Wqr[t] + b[t]
        float acc = Wqr_b[t];
        for (int d = 0; d < DD; d++) acc += query[b * DD + d] * Wqr[t * DD + d];
        g_Qq[b * DD + t] = acc;
    }
}

// -------- GEMM: C[M,128] = epi(A[M,128] @ WT[128,128]) --------
// WT is ALREADY transposed: layout [k][n] row-major.
// BM=128, 512 threads (16 warps), thread tile 4x8, packed f32x2 accumulators.
// k processed in chunks of 4 so A-reads are LDS.128 along k.
// mode 0: plain.  mode 1: relu(x + bias[n]), zeroed where deg[row]==0.
__global__ __launch_bounds__(512, 1)
void gemm128_kernel(const float* __restrict__ A, const float* __restrict__ WT,
                    const float* __restrict__ bias, const int* __restrict__ deg,
                    float* __restrict__ C, int M, int mode)
{
    extern __shared__ float smem[];
    float* sA = smem;             // 128 x 128 (row-major [m][k])
    float* sW = smem + DD * DD;   // 128 x 128 ([k][n])

    const int tid = threadIdx.x;
    const int m0 = blockIdx.x * 128;

    const float4* A4 = reinterpret_cast<const float4*>(A);
    float4* sA4 = reinterpret_cast<float4*>(sA);
    #pragma unroll
    for (int i = tid; i < DD * DD / 4; i += 512) {
        int row = i >> 5;
        int gr = m0 + row;
        float4 v = make_float4(0.f, 0.f, 0.f, 0.f);
        if (gr < M) v = A4[(size_t)gr * 32 + (i & 31)];
        sA4[i] = v;
    }
    const float4* W4 = reinterpret_cast<const float4*>(WT);
    float4* sW4 = reinterpret_cast<float4*>(sW);
    #pragma unroll
    for (int i = tid; i < DD * DD / 4; i += 512) sW4[i] = W4[i];
    __syncthreads();

    const int tx = tid & 15;        // col group: 8 cols (n) at tx*8
    const int ty = tid >> 4;        // row group: 4 rows (m) at ty*4
    const float* sAr = sA + ty * 4 * DD;
    const float* sWc = sW + tx * 8;

    unsigned long long acc[4][4];
    #pragma unroll
    for (int i = 0; i < 4; i++)
        #pragma unroll
        for (int j = 0; j < 4; j++) acc[i][j] = 0ULL;

    #pragma unroll 2
    for (int k = 0; k < DD; k += 4) {
        // 4 vector loads of A along k (warp-broadcast: 2 distinct addrs/warp)
        float4 a4[4];
        #pragma unroll
        for (int i = 0; i < 4; i++)
            a4[i] = *reinterpret_cast<const float4*>(sAr + i * DD + k);
        // 8 vector loads of W (4 k-steps x 2 halves)
        ulonglong2 w0[4], w1[4];
        #pragma unroll
        for (int kk = 0; kk < 4; kk++) {
            w0[kk] = *reinterpret_cast<const ulonglong2*>(sWc + (size_t)(k + kk) * DD);
            w1[kk] = *reinterpret_cast<const ulonglong2*>(sWc + (size_t)(k + kk) * DD + 4);
        }
        // 64 fma2 (128 FMA) per chunk
        #pragma unroll
        for (int kk = 0; kk < 4; kk++) {
            #pragma unroll
            for (int i = 0; i < 4; i++) {
                float a = (&a4[i].x)[kk];
                unsigned long long ad = pack2(a, a);
                fma2(acc[i][0], ad, w0[kk].x);
                fma2(acc[i][1], ad, w0[kk].y);
                fma2(acc[i][2], ad, w1[kk].x);
                fma2(acc[i][3], ad, w1[kk].y);
            }
        }
    }

    #pragma unroll
    for (int i = 0; i < 4; i++) {
        int row = m0 + ty * 4 + i;
        if (row >= M) continue;
        float out[8];
        #pragma unroll
        for (int j = 0; j < 4; j++) {
            float2 v = unpack2(acc[i][j]);
            out[2 * j] = v.x; out[2 * j + 1] = v.y;
        }
        if (mode == 1) {
            bool keep = deg[row] > 0;
            #pragma unroll
            for (int j = 0; j < 8; j++) {
                float x = fmaxf(out[j] + bias[tx * 8 + j], 0.f);
                out[j] = keep ? x : 0.f;
            }
        }
        float4* Crow = reinterpret_cast<float4*>(C + (size_t)row * DD + tx * 8);
        Crow[0] = make_float4(out[0], out[1], out[2], out[3]);
        Crow[1] = make_float4(out[4], out[5], out[6], out[7]);
    }
}

// -------- edge kernel: one warp per edge --------
// alpha = sigmoid( W_attn · relu(Hs[sub] + Rr[rel] + Qq[bat]) )
// agg[obj] += hidden[sub] * rela[rel] * alpha   (vector red.global)
__global__ __launch_bounds__(256)
void edge_kernel(const int4* __restrict__ edges, const float* __restrict__ Wattn,
                 const float* __restrict__ hidden, const float* __restrict__ rela, int E)
{
    int e = blockIdx.x * 8 + (threadIdx.x >> 5);
    if (e >= E) return;
    int lane = threadIdx.x & 31;
    int4 ed = edges[e];            // x=bat, y=sub(flat), z=rel, w=obj(flat)
    int c = lane * 4;

    float4 hs = *reinterpret_cast<const float4*>(g_Hs + (size_t)ed.y * DD + c);
    float4 rr = *reinterpret_cast<const float4*>(g_Rr + (size_t)ed.z * DD + c);
    float4 qq = *reinterpret_cast<const float4*>(g_Qq + (size_t)ed.x * DD + c);
    float4 wa = *reinterpret_cast<const float4*>(Wattn + c);

    float hx = fmaxf(hs.x + rr.x + qq.x, 0.f);
    float hy = fmaxf(hs.y + rr.y + qq.y, 0.f);
    float hz = fmaxf(hs.z + rr.z + qq.z, 0.f);
    float hw = fmaxf(hs.w + rr.w + qq.w, 0.f);
    float p = hx * wa.x + hy * wa.y + hz * wa.z + hw * wa.w;
    #pragma unroll
    for (int o = 16; o > 0; o >>= 1) p += __shfl_xor_sync(0xffffffffu, p, o);
    float alpha = 1.f / (1.f + __expf(-p));

    float4 mh = *reinterpret_cast<const float4*>(hidden + (size_t)ed.y * DD + c);
    float4 mr = *reinterpret_cast<const float4*>(rela + (size_t)ed.z * DD + c);
    float mx = mh.x * mr.x * alpha;
    float my = mh.y * mr.y * alpha;
    float mz = mh.z * mr.z * alpha;
    float mw = mh.w * mr.w * alpha;

    float* dst = g_agg + (size_t)ed.w * DD + c;
    asm volatile("red.global.add.v4.f32 [%0], {%1,%2,%3,%4};"
                 :: "l"(dst), "f"(mx), "f"(my), "f"(mz), "f"(mw) : "memory");
    if (lane == 0) atomicAdd(&g_deg[ed.w], 1);
}

// -------- launch --------
extern "C" void kernel_launch(void* const* d_in, const int* in_sizes, int n_in,
                              void* d_out, int out_size)
{
    const float* query  = (const float*)d_in[0];
    const float* hidden = (const float*)d_in[3];
    const int*   edges  = (const int*)d_in[4];
    const float* Ws     = (const float*)d_in[6];
    const float* Wr     = (const float*)d_in[7];
    const float* Wqr    = (const float*)d_in[8];
    const float* Wqr_b  = (const float*)d_in[9];
    const float* Wattn  = (const float*)d_in[10];
    const float* rela   = (const float*)d_in[11];
    const float* mlp1_w = (const float*)d_in[12];
    const float* mlp1_b = (const float*)d_in[13];
    const float* mlp2_w = (const float*)d_in[14];
    const float* mlp2_b = (const float*)d_in[15];

    int M = in_sizes[3] / DD;     // B*N = 200000
    int E = in_sizes[4] / 4;      // 600000
    int R = in_sizes[11] / DD;    // 200
    int B = in_sizes[0] / DD;     // 4

    void *aggp = nullptr, *degp = nullptr, *hsp = nullptr, *wfp = nullptr, *bfp = nullptr, *wstp = nullptr;
    cudaGetSymbolAddress(&aggp, g_agg);
    cudaGetSymbolAddress(&degp, g_deg);
    cudaGetSymbolAddress(&hsp,  g_Hs);
    cudaGetSymbolAddress(&wfp,  g_Wf);
    cudaGetSymbolAddress(&bfp,  g_bf);
    cudaGetSymbolAddress(&wstp, g_WsT);

    cudaMemsetAsync(aggp, 0, (size_t)M * DD * sizeof(float), 0);
    cudaMemsetAsync(degp, 0, (size_t)M * sizeof(int), 0);

    prep_kernel<<<2 * DD + R + B, DD>>>(mlp1_w, mlp1_b, mlp2_w, mlp2_b,
                                        rela, Wr, query, Wqr, Wqr_b, Ws, R, B);

    size_t smem = (size_t)2 * DD * DD * sizeof(float);   // 128 KB
    cudaFuncSetAttribute(gemm128_kernel, cudaFuncAttributeMaxDynamicSharedMemorySize, (int)smem);

    // Hs = hidden @ Ws^T   (g_WsT is Ws pre-transposed to [k][n])
    gemm128_kernel<<<(M + 127) / 128, 512, smem>>>(hidden, (const float*)wstp, nullptr, nullptr,
                                                   (float*)hsp, M, 0);
    // per-edge attention + scatter
    edge_kernel<<<(E + 7) / 8, 256>>>((const int4*)edges, Wattn, hidden, rela, E);

    // out = mask(deg>0) * relu(agg @ (mlp2·mlp1)^T + b')   (g_Wf pre-transposed)
    gemm128_kernel<<<(M + 127) / 128, 512, smem>>>((const float*)aggp, (const float*)wfp,
                                                   (const float*)bfp, (const int*)degp,
                                                   (float*)d_out, M, 1);
}

// round 6
// speedup vs baseline: 1.4857x; 1.4857x over previous
#include <cuda_runtime.h>
#include <cstdint>

#define DD 128
#define MAXM 200000
#define MAXR 256
#define MAXB 8

// -------- scratch (static device memory; no allocs allowed) --------
__device__ float g_Hs[(size_t)MAXM * DD];   // hidden @ Ws^T      (102.4 MB)
__device__ float g_agg[(size_t)MAXM * DD];  // segment_sum output (102.4 MB)
__device__ int   g_deg[MAXM];
__device__ float g_Rr[MAXR * DD];           // rela_embed @ Wr^T
__device__ float g_Qq[MAXB * DD];           // query @ Wqr^T + b
__device__ float g_Wf[DD * DD];             // (mlp2 @ mlp1)^T   -- stored [k][n]
__device__ float g_bf[DD];                  // mlp2 @ b1 + b2
__device__ float g_WsT[DD * DD];            // Ws_attn_w^T       -- stored [k][n]

// -------- packed f32x2 helpers (sm_103a FFMA2 pipe: 2 FMA / instr) --------
__device__ __forceinline__ unsigned long long pack2(float lo, float hi) {
    unsigned long long r;
    asm("mov.b64 %0, {%1,%2};" : "=l"(r) : "f"(lo), "f"(hi));
    return r;
}
__device__ __forceinline__ void fma2(unsigned long long& acc, unsigned long long a, unsigned long long b) {
    asm("fma.rn.f32x2 %0, %1, %2, %0;" : "+l"(acc) : "l"(a), "l"(b));
}
__device__ __forceinline__ float2 unpack2(unsigned long long v) {
    float lo, hi;
    asm("mov.b64 {%0,%1}, %2;" : "=f"(lo), "=f"(hi) : "l"(v));
    return make_float2(lo, hi);
}

// -------- tiny precompute: WfT, bf, Rr, Qq, WsT --------
__global__ void prep_kernel(const float* __restrict__ mlp1_w, const float* __restrict__ mlp1_b,
                            const float* __restrict__ mlp2_w, const float* __restrict__ mlp2_b,
                            const float* __restrict__ rela,   const float* __restrict__ Wr,
                            const float* __restrict__ query,  const float* __restrict__ Wqr,
                            const float* __restrict__ Wqr_b,  const float* __restrict__ Ws,
                            int R, int B)
{
    int t = threadIdx.x;
    int bx = blockIdx.x;
    if (bx < DD) {
        int i = bx;                           // output dim (n) of fused weight
        float acc = 0.f;
        for (int j = 0; j < DD; j++) acc += mlp2_w[i * DD + j] * mlp1_w[j * DD + t];
        g_Wf[t * DD + i] = acc;               // store TRANSPOSED: [k][n]
        __shared__ float s[DD];
        s[t] = mlp2_w[i * DD + t] * mlp1_b[t];
        __syncthreads();
        if (t == 0) {
            float b = 0.f;
            for (int j = 0; j < DD; j++) b += s[j];
            g_bf[i] = b + mlp2_b[i];
        }
    } else if (bx < 2 * DD) {
        int n = bx - DD;                      // transpose Ws: g_WsT[k][n] = Ws[n][k]
        g_WsT[t * DD + n] = Ws[n * DD + t];
    } else if (bx < 2 * DD + R) {
        int r = bx - 2 * DD;                  // Rr[r][t] = rela[r]·Wr[t]
        float acc = 0.f;
        for (int d = 0; d < DD; d++) acc += rela[r * DD + d] * Wr[t * DD + d];
        g_Rr[r * DD + t] = acc;
    } else {
        int b = bx - 2 * DD - R;              // Qq[b][t] = query[b]·Wqr[t] + b[t]
        float acc = Wqr_b[t];
        for (int d = 0; d < DD; d++) acc += query[b * DD + d] * Wqr[t * DD + d];
        g_Qq[b * DD + t] = acc;
    }
}

// -------- GEMM: C[M,128] = epi(A[M,128] @ WT[128,128]) --------
// WT is ALREADY transposed: layout [k][n] row-major.
// Tile BM=128 x BN=64 (N split over 2 CTAs), 256 threads, thread tile 8x4.
// smem = 64KB(A) + 32KB(W-half) = 96KB -> 2 CTAs/SM (16 warps, 4/SMSP).
// k in chunks of 4: A-reads are LDS.128 along k; per chunk 12 LDS / 64 fma2.
// mode 0: plain.  mode 1: relu(x + bias[n]), zeroed where deg[row]==0.
__global__ __launch_bounds__(256, 2)
void gemm128_kernel(const float* __restrict__ A, const float* __restrict__ WT,
                    const float* __restrict__ bias, const int* __restrict__ deg,
                    float* __restrict__ C, int M, int mode)
{
    extern __shared__ float smem[];
    float* sA = smem;               // 128(m) x 128(k)
    float* sW = smem + DD * DD;     // 128(k) x 64(n half)

    const int tid = threadIdx.x;
    const int mb = blockIdx.x >> 1;
    const int nb = blockIdx.x & 1;
    const int m0 = mb * 128;
    const int n0 = nb * 64;

    // load A tile: 128 rows x 32 float4
    const float4* A4 = reinterpret_cast<const float4*>(A);
    float4* sA4 = reinterpret_cast<float4*>(sA);
    #pragma unroll
    for (int i = tid; i < DD * DD / 4; i += 256) {
        int row = i >> 5;
        int gr = m0 + row;
        float4 v = make_float4(0.f, 0.f, 0.f, 0.f);
        if (gr < M) v = A4[(size_t)gr * 32 + (i & 31)];
        sA4[i] = v;
    }
    // load W half: 128 rows x 16 float4 (cols n0..n0+63)
    const float4* W4 = reinterpret_cast<const float4*>(WT);
    float4* sW4 = reinterpret_cast<float4*>(sW);
    #pragma unroll
    for (int i = tid; i < DD * 64 / 4; i += 256) {
        int row = i >> 4;
        sW4[i] = W4[row * 32 + nb * 16 + (i & 15)];
    }
    __syncthreads();

    const int tx = tid & 15;        // col group: 4 cols (n) at n0 + tx*4
    const int ty = tid >> 4;        // row group: 8 rows (m) at ty*8
    const float* sAr = sA + ty * 8 * DD;
    const float* sWc = sW + tx * 4;

    unsigned long long acc[8][2];
    #pragma unroll
    for (int i = 0; i < 8; i++) { acc[i][0] = 0ULL; acc[i][1] = 0ULL; }

    #pragma unroll 2
    for (int k = 0; k < DD; k += 4) {
        // 8 vector loads of A along k (warp-broadcast: 2 distinct addrs/warp)
        float4 a4[8];
        #pragma unroll
        for (int i = 0; i < 8; i++)
            a4[i] = *reinterpret_cast<const float4*>(sAr + i * DD + k);
        // 4 vector loads of W (one per k-step; smem row stride = 64)
        ulonglong2 w[4];
        #pragma unroll
        for (int kk = 0; kk < 4; kk++)
            w[kk] = *reinterpret_cast<const ulonglong2*>(sWc + (size_t)(k + kk) * 64);
        // 64 fma2 (128 FMA) per chunk
        #pragma unroll
        for (int kk = 0; kk < 4; kk++) {
            #pragma unroll
            for (int i = 0; i < 8; i++) {
                float a = (&a4[i].x)[kk];
                unsigned long long ad = pack2(a, a);
                fma2(acc[i][0], ad, w[kk].x);
                fma2(acc[i][1], ad, w[kk].y);
            }
        }
    }

    #pragma unroll
    for (int i = 0; i < 8; i++) {
        int row = m0 + ty * 8 + i;
        if (row >= M) continue;
        float out[4];
        float2 v0 = unpack2(acc[i][0]);
        float2 v1 = unpack2(acc[i][1]);
        out[0] = v0.x; out[1] = v0.y; out[2] = v1.x; out[3] = v1.y;
        if (mode == 1) {
            bool keep = deg[row] > 0;
            #pragma unroll
            for (int j = 0; j < 4; j++) {
                float x = fmaxf(out[j] + bias[n0 + tx * 4 + j], 0.f);
                out[j] = keep ? x : 0.f;
            }
        }
        *reinterpret_cast<float4*>(C + (size_t)row * DD + n0 + tx * 4) =
            make_float4(out[0], out[1], out[2], out[3]);
    }
}

// -------- edge kernel: one warp per edge --------
// alpha = sigmoid( W_attn · relu(Hs[sub] + Rr[rel] + Qq[bat]) )
// agg[obj] += hidden[sub] * rela[rel] * alpha   (vector red.global)
__global__ __launch_bounds__(256)
void edge_kernel(const int4* __restrict__ edges, const float* __restrict__ Wattn,
                 const float* __restrict__ hidden, const float* __restrict__ rela, int E)
{
    int e = blockIdx.x * 8 + (threadIdx.x >> 5);
    if (e >= E) return;
    int lane = threadIdx.x & 31;
    int4 ed = edges[e];            // x=bat, y=sub(flat), z=rel, w=obj(flat)
    int c = lane * 4;

    float4 hs = *reinterpret_cast<const float4*>(g_Hs + (size_t)ed.y * DD + c);
    float4 rr = *reinterpret_cast<const float4*>(g_Rr + (size_t)ed.z * DD + c);
    float4 qq = *reinterpret_cast<const float4*>(g_Qq + (size_t)ed.x * DD + c);
    float4 wa = *reinterpret_cast<const float4*>(Wattn + c);

    float hx = fmaxf(hs.x + rr.x + qq.x, 0.f);
    float hy = fmaxf(hs.y + rr.y + qq.y, 0.f);
    float hz = fmaxf(hs.z + rr.z + qq.z, 0.f);
    float hw = fmaxf(hs.w + rr.w + qq.w, 0.f);
    float p = hx * wa.x + hy * wa.y + hz * wa.z + hw * wa.w;
    #pragma unroll
    for (int o = 16; o > 0; o >>= 1) p += __shfl_xor_sync(0xffffffffu, p, o);
    float alpha = 1.f / (1.f + __expf(-p));

    float4 mh = *reinterpret_cast<const float4*>(hidden + (size_t)ed.y * DD + c);
    float4 mr = *reinterpret_cast<const float4*>(rela + (size_t)ed.z * DD + c);
    float mx = mh.x * mr.x * alpha;
    float my = mh.y * mr.y * alpha;
    float mz = mh.z * mr.z * alpha;
    float mw = mh.w * mr.w * alpha;

    float* dst = g_agg + (size_t)ed.w * DD + c;
    asm volatile("red.global.add.v4.f32 [%0], {%1,%2,%3,%4};"
                 :: "l"(dst), "f"(mx), "f"(my), "f"(mz), "f"(mw) : "memory");
    if (lane == 0) atomicAdd(&g_deg[ed.w], 1);
}

// -------- launch --------
extern "C" void kernel_launch(void* const* d_in, const int* in_sizes, int n_in,
                              void* d_out, int out_size)
{
    const float* query  = (const float*)d_in[0];
    const float* hidden = (const float*)d_in[3];
    const int*   edges  = (const int*)d_in[4];
    const float* Ws     = (const float*)d_in[6];
    const float* Wr     = (const float*)d_in[7];
    const float* Wqr    = (const float*)d_in[8];
    const float* Wqr_b  = (const float*)d_in[9];
    const float* Wattn  = (const float*)d_in[10];
    const float* rela   = (const float*)d_in[11];
    const float* mlp1_w = (const float*)d_in[12];
    const float* mlp1_b = (const float*)d_in[13];
    const float* mlp2_w = (const float*)d_in[14];
    const float* mlp2_b = (const float*)d_in[15];

    int M = in_sizes[3] / DD;     // B*N = 200000
    int E = in_sizes[4] / 4;      // 600000
    int R = in_sizes[11] / DD;    // 200
    int B = in_sizes[0] / DD;     // 4

    void *aggp = nullptr, *degp = nullptr, *hsp = nullptr, *wfp = nullptr, *bfp = nullptr, *wstp = nullptr;
    cudaGetSymbolAddress(&aggp, g_agg);
    cudaGetSymbolAddress(&degp, g_deg);
    cudaGetSymbolAddress(&hsp,  g_Hs);
    cudaGetSymbolAddress(&wfp,  g_Wf);
    cudaGetSymbolAddress(&bfp,  g_bf);
    cudaGetSymbolAddress(&wstp, g_WsT);

    cudaMemsetAsync(aggp, 0, (size_t)M * DD * sizeof(float), 0);
    cudaMemsetAsync(degp, 0, (size_t)M * sizeof(int), 0);

    prep_kernel<<<2 * DD + R + B, DD>>>(mlp1_w, mlp1_b, mlp2_w, mlp2_b,
                                        rela, Wr, query, Wqr, Wqr_b, Ws, R, B);

    size_t smem = (size_t)(DD * DD + DD * 64) * sizeof(float);   // 96 KB
    cudaFuncSetAttribute(gemm128_kernel, cudaFuncAttributeMaxDynamicSharedMemorySize, (int)smem);

    int grid = ((M + 127) / 128) * 2;    // x2 for the two N-halves

    // Hs = hidden @ Ws^T   (g_WsT is Ws pre-transposed to [k][n])
    gemm128_kernel<<<grid, 256, smem>>>(hidden, (const float*)wstp, nullptr, nullptr,
                                        (float*)hsp, M, 0);
    // per-edge attention + scatter
    edge_kernel<<<(E + 7) / 8, 256>>>((const int4*)edges, Wattn, hidden, rela, E);

    // out = mask(deg>0) * relu(agg @ (mlp2·mlp1)^T + b')   (g_Wf pre-transposed)
    gemm128_kernel<<<grid, 256, smem>>>((const float*)aggp, (const float*)wfp,
                                        (const float*)bfp, (const int*)degp,
                                        (float*)d_out, M, 1);
}